// round 17
// baseline (speedup 1.0000x reference)
#include <cuda_runtime.h>

#define NSAMP 16384
#define PTS   20
#define DIM   128
#define KNN   5
#define NANCH (NSAMP * PTS)
#define EDGES (NANCH * KNN)

#define SPB 3
#define NTH 128                        // 4 warps; 120 phase-2 workers
#define RSTRIDE 136                    // [64 dims][4 pad][64 dims][4 pad]
#define HOFF 68                        // word offset of half 1
#define SAMP_STRIDE (PTS * RSTRIDE + 8)   // 2728 (mod 32 == 8)
#define SMX_FLOATS (SPB * SAMP_STRIDE)    // 8184 words = 32.7 KB
#define PDQ 40                            // per-q: [h0 p0..19][h1 p0..19]
#define PD_PER_S (PTS * PDQ + 8)          // 808 words (mod 32 == 8: desamples banks)
#define SMPD_FLOATS (SPB * PD_PER_S)      // 2424 words = 9.7 KB

__device__ __forceinline__ void fma2(unsigned long long &acc,
                                     unsigned long long a,
                                     unsigned long long b) {
    asm("fma.rn.f32x2 %0, %1, %2, %0;" : "+l"(acc) : "l"(a), "l"(b));
}

// (a0+a1) + (a2+a3) over a 64-dim half: verified-safe order (R7..R16)
__device__ __forceinline__ float chainsum(unsigned long long acc01,
                                          unsigned long long acc23) {
    float2 lo = *reinterpret_cast<float2*>(&acc01);
    float2 hi = *reinterpret_cast<float2*>(&acc23);
    return (lo.x + lo.y) + (hi.x + hi.y);
}

__global__ void __launch_bounds__(NTH, 5)
knn_kernel(const float* __restrict__ x, float* __restrict__ out, int cap) {
    __shared__ __align__(16) float smx[SMX_FLOATS];
    __shared__ __align__(16) float smpd[SMPD_FLOATS];
    __shared__ float smnorm[SPB * PTS];

    const int tid = threadIdx.x;
    const int bs0 = blockIdx.x * SPB;

    // ---- Stage 3 samples gmem -> smem (R12-proven split-row layout) ----
    {
        const float4* xin = reinterpret_cast<const float4*>(x)
                          + (size_t)bs0 * (PTS * DIM / 4);
        #pragma unroll
        for (int t = tid; t < SPB * PTS * (DIM / 4); t += NTH) {
            int rc  = t >> 5;                   // row 0..59
            int e   = t & 31;                   // float4 idx in source row
            int s   = rc / PTS;
            int row = rc - s * PTS;
            if (bs0 + s < NSAMP) {
                float4 v = xin[(size_t)rc * 32 + e];
                int dest = s * SAMP_STRIDE + row * RSTRIDE + 4 * e + (e >= 16 ? 4 : 0);
                *reinterpret_cast<float4*>(&smx[dest]) = v;
            }
        }
    }
    __syncthreads();

    // ---- Phase 2: worker (s, h, p) = ONE anchor p on half h ----
    // lane mapping keeps 16-lane groups h-split for broadcast-friendly LDS
    {
        const int w  = tid >> 5;                 // warp 0..3
        const int l  = tid & 31;
        const int j  = w * 16 + (l & 15);        // pair-slot 0..63 (60 used)
        const int h  = l >> 4;                   // half 0/1
        const bool act2 = (j < SPB * PTS);
        const int s = act2 ? (j / PTS) : 0;
        const int p = act2 ? (j - s * PTS) : 0;
        if (act2 && (bs0 + s < NSAMP)) {
            const float* base = &smx[s * SAMP_STRIDE + h * HOFF];
            unsigned long long xp[32];           // own half-row: 64 regs
            {
                const ulonglong2* pr =
                    reinterpret_cast<const ulonglong2*>(base + p * RSTRIDE);
                #pragma unroll
                for (int c = 0; c < 16; c++) {
                    ulonglong2 v = pr[c];
                    xp[2 * c]     = v.x;
                    xp[2 * c + 1] = v.y;
                }
            }
            float* pds = &smpd[s * PD_PER_S];
            const int slot = h * PTS + p;
            #pragma unroll 1
            for (int q = 0; q < PTS; q++) {
                const ulonglong2* xq =
                    reinterpret_cast<const ulonglong2*>(base + q * RSTRIDE);
                unsigned long long a01 = 0ull, a23 = 0ull;
                #pragma unroll
                for (int b = 0; b < 4; b++) {    // 4 batches of 4 chunks
                    ulonglong2 v[4];
                    #pragma unroll
                    for (int k = 0; k < 4; k++) v[k] = xq[4 * b + k];
                    #pragma unroll
                    for (int k = 0; k < 4; k++) {   // e ascending: frozen order
                        fma2(a01, xp[2 * (4 * b + k)],     v[k].x);
                        fma2(a23, xp[2 * (4 * b + k) + 1], v[k].y);
                    }
                }
                pds[q * PDQ + slot] = chainsum(a01, a23);
            }
        }
    }
    __syncthreads();

    // ---- Phase 3a: norms from the diagonal (h0 + h1, verified order) ----
    const bool act3 = (tid < SPB * PTS);         // 60 threads
    const int s3 = act3 ? (tid / PTS) : 0;
    const int p3 = act3 ? (tid - s3 * PTS) : 0;
    const bool valid3 = act3 && (bs0 + s3 < NSAMP);
    if (valid3) {
        const float* pds = &smpd[s3 * PD_PER_S];
        smnorm[s3 * PTS + p3] = pds[p3 * PDQ + p3] + pds[p3 * PDQ + PTS + p3];
    }
    __syncthreads();

    // ---- Phase 3b: assemble dots; exact (d2, q)-lex top-5; emit ----
    if (valid3) {
        const float* pds = &smpd[s3 * PD_PER_S];
        const float sqp = smnorm[s3 * PTS + p3];

        float kd[KNN];
        int   ki[KNN];
        #pragma unroll
        for (int m = 0; m < KNN; m++) { kd[m] = __int_as_float(0x7F800000); ki[m] = 0; }

        #pragma unroll
        for (int q = 0; q < PTS; q++) {
            const float dot = pds[q * PDQ + p3] + pds[q * PDQ + PTS + p3]; // h0+h1
            const float sqq = smnorm[s3 * PTS + q];
            float dd = fmaxf(sqp + sqq - 2.0f * dot, 0.0f);   // ref clamp
            if (q == p3) dd = __int_as_float(0x7F800000);     // exclude self
            float ck = dd; int ci = q;
            #pragma unroll
            for (int m = 0; m < KNN; m++) {       // stable insertion (strict <)
                bool sw = ck < kd[m];
                float tk = kd[m]; int ti = ki[m];
                kd[m] = sw ? ck : tk;  ki[m] = sw ? ci : ti;
                ck    = sw ? tk : ck;  ci    = sw ? ti : ci;
            }
        }

        const int wg  = (bs0 + s3) * PTS + p3;
        const int obw = wg * KNN;
        const float pf = (float)p3;
        #pragma unroll
        for (int rr = 0; rr < KNN; rr++) {
            int iu = obw + rr;
            int iv = EDGES + obw + rr;
            if (iu < cap) out[iu] = pf;
            if (iv < cap) out[iv] = (float)ki[rr];
        }
    }
}

extern "C" void kernel_launch(void* const* d_in, const int* in_sizes, int n_in,
                              void* d_out, int out_size) {
    const float* x = (const float*)d_in[0];
    float* out = (float*)d_out;

    int cap = 2 * EDGES;
    if (out_size > 0 && out_size < 2 * EDGES) cap = out_size;

    const int grid = (NSAMP + SPB - 1) / SPB;   // 5462
    knn_kernel<<<grid, NTH>>>(x, out, cap);
}